// round 6
// baseline (speedup 1.0000x reference)
#include <cuda_runtime.h>

#define BATCH 4
#define HEADS 8
#define MID 16
#define HALF 8
#define G 4
#define COUT 64
#define WDIM 28
#define NPOS 784
#define NREL 110
#define QLOG2 0.8329091229351039f   // (1/sqrt(3)) * log2(e)

typedef unsigned long long ull;

__device__ __forceinline__ ull pk2(float lo, float hi){ ull r; asm("mov.b64 %0,{%1,%2};":"=l"(r):"f"(lo),"f"(hi)); return r; }
__device__ __forceinline__ void upk2(ull v, float& lo, float& hi){ asm("mov.b64 {%0,%1},%2;":"=f"(lo),"=f"(hi):"l"(v)); }
__device__ __forceinline__ ull fma2_(ull a, ull b, ull c){ ull d; asm("fma.rn.f32x2 %0,%1,%2,%3;":"=l"(d):"l"(a),"l"(b),"l"(c)); return d; }
__device__ __forceinline__ ull mul2_(ull a, ull b){ ull d; asm("mul.rn.f32x2 %0,%1,%2;":"=l"(d):"l"(a),"l"(b)); return d; }
__device__ __forceinline__ ull add2_(ull a, ull b){ ull d; asm("add.rn.f32x2 %0,%1,%2;":"=l"(d):"l"(a),"l"(b)); return d; }
__device__ __forceinline__ float ex2_(float x){ float r; asm("ex2.approx.f32 %0,%1;":"=f"(r):"f"(x)); return r; }

// ---------------- device scratch ----------------
__device__ float d_q[BATCH*HEADS*NPOS*MID];   // [bh][pos][16]
__device__ float d_k[BATCH*HEADS*NPOS*MID];
__device__ float d_v[BATCH*HEADS*NPOS*MID];
__device__ float d_Er[NREL*HALF];
__device__ float d_Ec[NREL*HALF];
__device__ float d_outv[BATCH*G*NPOS*(MID*HEADS)];   // [b][g][pos][m*8+h]

// ---------------- embedding MLP ----------------
__global__ void embed_kernel(
    const float* __restrict__ w1r, const float* __restrict__ b1r,
    const float* __restrict__ gr,  const float* __restrict__ ber,
    const float* __restrict__ w2r, const float* __restrict__ b2r,
    const float* __restrict__ w1c, const float* __restrict__ b1c,
    const float* __restrict__ gc,  const float* __restrict__ bec,
    const float* __restrict__ w2c, const float* __restrict__ b2c)
{
    int t = threadIdx.x;
    if (t >= 2*NREL) return;
    bool isRow = (t < NREL);
    int a = isRow ? t : t - NREL;
    const float* w1 = isRow ? w1r : w1c;
    const float* b1 = isRow ? b1r : b1c;
    const float* ga = isRow ? gr  : gc;
    const float* be = isRow ? ber : bec;
    const float* w2 = isRow ? w2r : w2c;
    const float* b2 = isRow ? b2r : b2c;

    float u;
    if (a < 55) u = a * (2.0f/54.0f) - 1.0f;
    else        u = -((a-55) * (2.0f/54.0f) - 1.0f);

    float h[16];
    float mu = 0.f;
#pragma unroll
    for (int c = 0; c < 16; c++) { h[c] = u*w1[c] + b1[c]; mu += h[c]; }
    mu *= (1.0f/16.0f);
    float var = 0.f;
#pragma unroll
    for (int c = 0; c < 16; c++) { float d = h[c]-mu; var += d*d; }
    var *= (1.0f/16.0f);
    float inv = rsqrtf(var + 1e-5f);
#pragma unroll
    for (int c = 0; c < 16; c++) {
        float hn = ga[c]*(h[c]-mu)*inv + be[c];
        h[c] = hn / (1.0f + expf(-hn));
    }
    float* out = isRow ? d_Er : d_Ec;
#pragma unroll
    for (int d = 0; d < HALF; d++) {
        float s = b2[d];
#pragma unroll
        for (int c = 0; c < 16; c++) s += h[c]*w2[d*16+c];
        out[a*HALF + d] = s;
    }
}

// ---------------- q/k/v 1x1 conv, output [bh][pos][16] ----------------
__global__ void qkv_kernel(
    const float* __restrict__ x,
    const float* __restrict__ wq, const float* __restrict__ bq,
    const float* __restrict__ wk, const float* __restrict__ bk,
    const float* __restrict__ wv, const float* __restrict__ bv)
{
    int idx = blockIdx.x*blockDim.x + threadIdx.x;
    if (idx >= BATCH*HEADS*NPOS*4) return;
    int mg  = idx & 3;
    int r   = idx >> 2;
    int pos = r % NPOS;
    int r2  = r / NPOS;
    int h   = r2 & 7;
    int b   = r2 >> 3;

    float x0 = x[(b*3+0)*NPOS + pos];
    float x1 = x[(b*3+1)*NPOS + pos];
    float x2 = x[(b*3+2)*NPOS + pos];

    float4 qv, kv, vv;
    float* qp = (float*)&qv; float* kp = (float*)&kv; float* vp = (float*)&vv;
#pragma unroll
    for (int mi = 0; mi < 4; mi++) {
        int o = (mg*4 + mi)*8 + h;
        qp[mi] = bq[o] + wq[o*3+0]*x0 + wq[o*3+1]*x1 + wq[o*3+2]*x2;
        kp[mi] = bk[o] + wk[o*3+0]*x0 + wk[o*3+1]*x1 + wk[o*3+2]*x2;
        vp[mi] = bv[o] + wv[o*3+0]*x0 + wv[o*3+1]*x1 + wv[o*3+2]*x2;
    }
    size_t dst4 = ((size_t)(b*HEADS + h)*NPOS + pos)*4 + mg;
    ((float4*)d_q)[dst4] = qv;
    ((float4*)d_k)[dst4] = kv;
    ((float4*)d_v)[dst4] = vv;
}

// ---------------- fused attention: CTA per (b,h,i), 4 warps, 7 j each ----------------
// smem float4: ksh[3136] | vsh[3136] | tbl[4*56] | 1 (norm int)
#define ATTN_SMEM_BYTES ((6272 + 4*56)*16 + 16)

__global__ void __launch_bounds__(128, 2) attn_kernel()
{
    extern __shared__ float4 sm4[];
    float4* ksh = sm4;            // [mb*784 + pos]
    float4* vsh = sm4 + 3136;
    float4* tbl = sm4 + 6272;     // [w*56 + a] : (fR[a], fC[a], fR[a+55], fC[a+55])
    int*  ctrl  = (int*)(sm4 + 6272 + 4*56);

    int t    = threadIdx.x;
    int w    = t >> 5;
    int lane = t & 31;
    int bx = blockIdx.x;
    int i  = bx % WDIM;
    int h  = (bx / WDIM) % HEADS;
    int b  = bx / (WDIM*HEADS);
    int bh = b*HEADS + h;

    const float4* gk4 = (const float4*)(d_k + (size_t)bh*NPOS*MID);
    const float4* gv4 = (const float4*)(d_v + (size_t)bh*NPOS*MID);
    const float*  gq  = d_q + (size_t)bh*NPOS*MID;

    if (t == 0) *ctrl = 0;
    for (int idx = t; idx < 3136; idx += 128) {
        int mb = idx & 3, pos = idx >> 2;
        ksh[mb*NPOS + pos] = gk4[idx];
        vsh[mb*NPOS + pos] = gv4[idx];
    }
    __syncthreads();

    // max ||k||^2
    {
        float mx = 0.f;
        for (int pos = t; pos < NPOS; pos += 128) {
            float4 k0 = ksh[pos], k1 = ksh[NPOS+pos], k2 = ksh[2*NPOS+pos], k3 = ksh[3*NPOS+pos];
            float n2 = k0.x*k0.x + k0.y*k0.y + k0.z*k0.z + k0.w*k0.w
                     + k1.x*k1.x + k1.y*k1.y + k1.z*k1.z + k1.w*k1.w
                     + k2.x*k2.x + k2.y*k2.y + k2.z*k2.z + k2.w*k2.w
                     + k3.x*k3.x + k3.y*k3.y + k3.z*k3.z + k3.w*k3.w;
            mx = fmaxf(mx, n2);
        }
#pragma unroll
        for (int off = 16; off; off >>= 1) mx = fmaxf(mx, __shfl_xor_sync(0xffffffffu, mx, off));
        if (lane == 0) atomicMax(ctrl, __float_as_int(mx));
    }
    __syncthreads();
    float maxknorm = sqrtf(__int_as_float(*ctrl));

    float* tblw = (float*)(tbl + w*56);
    const ulonglong2* K2 = (const ulonglong2*)ksh;
    const ulonglong2* V2 = (const ulonglong2*)vsh;

    for (int jj = 0; jj < 7; jj++) {
        int j = w*7 + jj;

        // q, scaled into log2 domain
        float q[16];
        {
            const float4* gq4 = (const float4*)(gq + ((size_t)(i*WDIM + j))*16);
            float4 a0 = gq4[0], a1 = gq4[1], a2 = gq4[2], a3 = gq4[3];
            q[0]=a0.x*QLOG2; q[1]=a0.y*QLOG2; q[2]=a0.z*QLOG2; q[3]=a0.w*QLOG2;
            q[4]=a1.x*QLOG2; q[5]=a1.y*QLOG2; q[6]=a1.z*QLOG2; q[7]=a1.w*QLOG2;
            q[8]=a2.x*QLOG2; q[9]=a2.y*QLOG2; q[10]=a2.z*QLOG2; q[11]=a2.w*QLOG2;
            q[12]=a3.x*QLOG2; q[13]=a3.y*QLOG2; q[14]=a3.z*QLOG2; q[15]=a3.w*QLOG2;
        }
        float qn = 0.f;
#pragma unroll
        for (int m = 0; m < 16; m++) qn += q[m]*q[m];

        // per-warp fused table + maxima
        __syncwarp();
        float mR = -1e30f, mC = -1e30f;
        for (int a = lane; a < NREL; a += 32) {
            const float4* er = (const float4*)(d_Er + a*8);
            float4 e0 = er[0], e1 = er[1];
            float fr = q[0]*e0.x + q[1]*e0.y + q[2]*e0.z + q[3]*e0.w
                     + q[4]*e1.x + q[5]*e1.y + q[6]*e1.z + q[7]*e1.w;
            const float4* ec = (const float4*)(d_Ec + a*8);
            float4 c0 = ec[0], c1 = ec[1];
            float fc = q[8]*c0.x + q[9]*c0.y + q[10]*c0.z + q[11]*c0.w
                     + q[12]*c1.x + q[13]*c1.y + q[14]*c1.z + q[15]*c1.w;
            mR = fmaxf(mR, fr); mC = fmaxf(mC, fc);
            if (a < 55) { tblw[a*4+0] = fr; tblw[a*4+1] = fc; }
            else        { tblw[(a-55)*4+2] = fr; tblw[(a-55)*4+3] = fc; }
        }
#pragma unroll
        for (int off = 16; off; off >>= 1) {
            mR = fmaxf(mR, __shfl_xor_sync(0xffffffffu, mR, off));
            mC = fmaxf(mC, __shfl_xor_sync(0xffffffffu, mC, off));
        }
        float negM = -(sqrtf(qn)*maxknorm + mR + mC);
        __syncwarp();

        ull q2[8];
#pragma unroll
        for (int p = 0; p < 8; p++) q2[p] = pk2(q[2*p], q[2*p+1]);

        // per-lane fixed-C preload (lanes 28-31 masked)
        bool valid = lane < 28;
        int lanec = valid ? lane : 27;
        int C = lanec - j + 27;
        float4 tc = tbl[w*56 + C];
        float cl0 = tc.y, cl1 = tc.z, cl2 = tc.w, cl3 = tc.x;
        if (!valid) { cl0 = cl1 = cl2 = cl3 = -1e30f; }

        ull acc[32];
#pragma unroll
        for (int v = 0; v < 32; v++) acc[v] = 0ull;
        float sm0 = 0.f, sm1 = 0.f, sm2 = 0.f, sm3 = 0.f;

#pragma unroll 4
        for (int kk = 0; kk < WDIM; kk++) {
            int pos = kk*WDIM + lanec;
            ulonglong2 k0 = K2[pos], k1 = K2[NPOS+pos], k2 = K2[2*NPOS+pos], k3 = K2[3*NPOS+pos];
            ull qa = mul2_(q2[0], k0.x);
            qa = fma2_(q2[1], k0.y, qa);
            qa = fma2_(q2[2], k1.x, qa);
            qa = fma2_(q2[3], k1.y, qa);
            qa = fma2_(q2[4], k2.x, qa);
            qa = fma2_(q2[5], k2.y, qa);
            qa = fma2_(q2[6], k3.x, qa);
            qa = fma2_(q2[7], k3.y, qa);
            float qlo, qhi; upk2(qa, qlo, qhi);
            float qk = qlo + qhi + negM;

            float4 tu = tbl[w*56 + (kk - i + 27)];   // warp-uniform broadcast
            float e0 = ex2_(qk + tu.x + cl0);
            float e1 = ex2_(qk + tu.y + cl1);
            float e2 = ex2_(qk + tu.z + cl2);
            float e3 = ex2_(qk + tu.w + cl3);
            sm0 += e0; sm1 += e1; sm2 += e2; sm3 += e3;

            ull eb0 = pk2(e0,e0), eb1 = pk2(e1,e1), eb2 = pk2(e2,e2), eb3 = pk2(e3,e3);
            ulonglong2 v0 = V2[pos], v1 = V2[NPOS+pos], v2 = V2[2*NPOS+pos], v3 = V2[3*NPOS+pos];

            acc[0]  = fma2_(eb0, v0.x, acc[0]);   acc[1]  = fma2_(eb0, v0.y, acc[1]);
            acc[2]  = fma2_(eb0, v1.x, acc[2]);   acc[3]  = fma2_(eb0, v1.y, acc[3]);
            acc[4]  = fma2_(eb0, v2.x, acc[4]);   acc[5]  = fma2_(eb0, v2.y, acc[5]);
            acc[6]  = fma2_(eb0, v3.x, acc[6]);   acc[7]  = fma2_(eb0, v3.y, acc[7]);
            acc[8]  = fma2_(eb1, v0.x, acc[8]);   acc[9]  = fma2_(eb1, v0.y, acc[9]);
            acc[10] = fma2_(eb1, v1.x, acc[10]);  acc[11] = fma2_(eb1, v1.y, acc[11]);
            acc[12] = fma2_(eb1, v2.x, acc[12]);  acc[13] = fma2_(eb1, v2.y, acc[13]);
            acc[14] = fma2_(eb1, v3.x, acc[14]);  acc[15] = fma2_(eb1, v3.y, acc[15]);
            acc[16] = fma2_(eb2, v0.x, acc[16]);  acc[17] = fma2_(eb2, v0.y, acc[17]);
            acc[18] = fma2_(eb2, v1.x, acc[18]);  acc[19] = fma2_(eb2, v1.y, acc[19]);
            acc[20] = fma2_(eb2, v2.x, acc[20]);  acc[21] = fma2_(eb2, v2.y, acc[21]);
            acc[22] = fma2_(eb2, v3.x, acc[22]);  acc[23] = fma2_(eb2, v3.y, acc[23]);
            acc[24] = fma2_(eb3, v0.x, acc[24]);  acc[25] = fma2_(eb3, v0.y, acc[25]);
            acc[26] = fma2_(eb3, v1.x, acc[26]);  acc[27] = fma2_(eb3, v1.y, acc[27]);
            acc[28] = fma2_(eb3, v2.x, acc[28]);  acc[29] = fma2_(eb3, v2.y, acc[29]);
            acc[30] = fma2_(eb3, v3.x, acc[30]);  acc[31] = fma2_(eb3, v3.y, acc[31]);
        }

        float sums[4] = {sm0, sm1, sm2, sm3};
#pragma unroll
        for (int gg = 0; gg < 4; gg++)
#pragma unroll
            for (int off = 16; off; off >>= 1)
                sums[gg] += __shfl_xor_sync(0xffffffffu, sums[gg], off);

        // value-halving butterfly: lane L ends holding packed value #L
#define RSTEP64(B, NN) { unsigned up = lane & (B);                                  \
        _Pragma("unroll") for (int v = 0; v < (NN); v++) {                          \
            ull send = up ? acc[v] : acc[v+(NN)];                                   \
            ull recv = __shfl_xor_sync(0xffffffffu, send, (B));                     \
            ull keep = up ? acc[v+(NN)] : acc[v];                                   \
            acc[v] = add2_(keep, recv); } }
        RSTEP64(16,16) RSTEP64(8,8) RSTEP64(4,4) RSTEP64(2,2) RSTEP64(1,1)
#undef RSTEP64

        int g  = lane >> 3;
        int mp = lane & 7;
        float f0, f1; upk2(acc[0], f0, f1);
        float inv; asm("rcp.approx.f32 %0,%1;":"=f"(inv):"f"(sums[g]));
        size_t base = (((size_t)(b*G + g)*NPOS) + i*WDIM + j)*128 + mp*16 + h;
        d_outv[base]     = f0*inv;
        d_outv[base + 8] = f1*inv;
    }
}

// ---------------- output 1x1 conv: 32x64 tiles, single wave ----------------
#define XPAD 34
#define WPAD 68
#define OUT_SMEM_BYTES ((128*XPAD + 128*WPAD)*4)
__global__ void __launch_bounds__(256, 4) out_gemm(const float* __restrict__ wout,
                                                   const float* __restrict__ bout,
                                                   float* __restrict__ out)
{
    extern __shared__ float osh[];
    float* Xs = osh;              // [k][r], stride XPAD, 32 rows
    float* Ws = osh + 128*XPAD;   // [k][c], stride WPAD, 64 cols

    int t = threadIdx.x;
    int Rbase = blockIdx.x * 32;

    for (int idx = t; idx < 1024; idx += 256) {
        int r = idx & 31, c4 = idx >> 5;
        float4 val = ((const float4*)d_outv)[(size_t)(Rbase + r)*32 + c4];
        Xs[(4*c4+0)*XPAD + r] = val.x;
        Xs[(4*c4+1)*XPAD + r] = val.y;
        Xs[(4*c4+2)*XPAD + r] = val.z;
        Xs[(4*c4+3)*XPAD + r] = val.w;
    }
    for (int idx = t; idx < 2048; idx += 256) {
        int o = idx & 63, c4 = idx >> 6;
        float4 val = ((const float4*)wout)[o*32 + c4];
        Ws[(4*c4+0)*WPAD + o] = val.x;
        Ws[(4*c4+1)*WPAD + o] = val.y;
        Ws[(4*c4+2)*WPAD + o] = val.z;
        Ws[(4*c4+3)*WPAD + o] = val.w;
    }
    __syncthreads();

    int tx = t & 15, ty = t >> 4;   // rows 2tx..2tx+1, cols 4ty..4ty+3
    float a0c0=0,a0c1=0,a0c2=0,a0c3=0,a1c0=0,a1c1=0,a1c2=0,a1c3=0;

#pragma unroll 8
    for (int k = 0; k < 128; k++) {
        float2 av = *(const float2*)&Xs[k*XPAD + 2*tx];
        float4 bv = *(const float4*)&Ws[k*WPAD + 4*ty];
        a0c0 += av.x*bv.x; a0c1 += av.x*bv.y; a0c2 += av.x*bv.z; a0c3 += av.x*bv.w;
        a1c0 += av.y*bv.x; a1c1 += av.y*bv.y; a1c2 += av.y*bv.z; a1c3 += av.y*bv.w;
    }

    float bia0 = bout[4*ty+0], bia1 = bout[4*ty+1], bia2 = bout[4*ty+2], bia3 = bout[4*ty+3];
    float rr[2][4] = {{a0c0+bia0,a0c1+bia1,a0c2+bia2,a0c3+bia3},
                      {a1c0+bia0,a1c1+bia1,a1c2+bia2,a1c3+bia3}};

#pragma unroll
    for (int ri = 0; ri < 2; ri++) {
        int R = Rbase + 2*tx + ri;
        int bb = R / (G*NPOS);
        int rem = R - bb*(G*NPOS);
        int g = rem / NPOS;
        int pos = rem - g*NPOS;
        size_t ob = (((size_t)(bb*COUT + 4*ty))*G + g)*NPOS + pos;
#pragma unroll
        for (int ci = 0; ci < 4; ci++)
            out[ob + (size_t)ci*G*NPOS] = rr[ri][ci];
    }
}

// ---------------- launch ----------------
extern "C" void kernel_launch(void* const* d_in, const int* in_sizes, int n_in,
                              void* d_out, int out_size)
{
    const float* x     = (const float*)d_in[0];
    const float* wq    = (const float*)d_in[1];
    const float* bq    = (const float*)d_in[2];
    const float* wk    = (const float*)d_in[3];
    const float* bk    = (const float*)d_in[4];
    const float* wv    = (const float*)d_in[5];
    const float* bv    = (const float*)d_in[6];
    const float* w_out = (const float*)d_in[7];
    const float* b_out = (const float*)d_in[8];
    const float* row_w1 = (const float*)d_in[9];
    const float* row_b1 = (const float*)d_in[10];
    const float* row_g  = (const float*)d_in[11];
    const float* row_be = (const float*)d_in[12];
    const float* row_w2 = (const float*)d_in[13];
    const float* row_b2 = (const float*)d_in[14];
    const float* col_w1 = (const float*)d_in[15];
    const float* col_b1 = (const float*)d_in[16];
    const float* col_g  = (const float*)d_in[17];
    const float* col_be = (const float*)d_in[18];
    const float* col_w2 = (const float*)d_in[19];
    const float* col_b2 = (const float*)d_in[20];

    cudaFuncSetAttribute(attn_kernel, cudaFuncAttributeMaxDynamicSharedMemorySize, ATTN_SMEM_BYTES);
    cudaFuncSetAttribute(out_gemm,    cudaFuncAttributeMaxDynamicSharedMemorySize, OUT_SMEM_BYTES);

    embed_kernel<<<1, 256>>>(row_w1, row_b1, row_g, row_be, row_w2, row_b2,
                             col_w1, col_b1, col_g, col_be, col_w2, col_b2);

    int qkv_threads = BATCH*HEADS*NPOS*4;
    qkv_kernel<<<(qkv_threads + 255)/256, 256>>>(x, wq, bq, wk, bk, wv, bv);

    attn_kernel<<<BATCH*HEADS*WDIM, 128, ATTN_SMEM_BYTES>>>();

    out_gemm<<<392, 256, OUT_SMEM_BYTES>>>(w_out, b_out, (float*)d_out);
}

// round 9
// speedup vs baseline: 1.6113x; 1.6113x over previous
#include <cuda_runtime.h>

#define BATCH 4
#define HEADS 8
#define MID 16
#define HALF 8
#define G 4
#define COUT 64
#define WDIM 28
#define NPOS 784
#define NREL 110
#define QLOG2 0.8329091229351039f   // (1/sqrt(3)) * log2(e)

typedef unsigned long long ull;

__device__ __forceinline__ ull pk2(float lo, float hi){ ull r; asm("mov.b64 %0,{%1,%2};":"=l"(r):"f"(lo),"f"(hi)); return r; }
__device__ __forceinline__ void upk2(ull v, float& lo, float& hi){ asm("mov.b64 {%0,%1},%2;":"=f"(lo),"=f"(hi):"l"(v)); }
__device__ __forceinline__ ull fma2_(ull a, ull b, ull c){ ull d; asm("fma.rn.f32x2 %0,%1,%2,%3;":"=l"(d):"l"(a),"l"(b),"l"(c)); return d; }
__device__ __forceinline__ float ex2_(float x){ float r; asm("ex2.approx.f32 %0,%1;":"=f"(r):"f"(x)); return r; }

// ---------------- device scratch ----------------
__device__ float d_q[BATCH*HEADS*NPOS*MID];   // [bh][pos][16]
__device__ float d_k[BATCH*HEADS*NPOS*MID];
__device__ float d_v[BATCH*HEADS*NPOS*MID];
__device__ float d_Er[NREL*HALF];
__device__ float d_Ec[NREL*HALF];
__device__ float d_outv[BATCH*G*NPOS*(MID*HEADS)];   // [b][g][pos][m*8+h]

// ---------------- embedding MLP ----------------
__global__ void embed_kernel(
    const float* __restrict__ w1r, const float* __restrict__ b1r,
    const float* __restrict__ gr,  const float* __restrict__ ber,
    const float* __restrict__ w2r, const float* __restrict__ b2r,
    const float* __restrict__ w1c, const float* __restrict__ b1c,
    const float* __restrict__ gc,  const float* __restrict__ bec,
    const float* __restrict__ w2c, const float* __restrict__ b2c)
{
    int t = threadIdx.x;
    if (t >= 2*NREL) return;
    bool isRow = (t < NREL);
    int a = isRow ? t : t - NREL;
    const float* w1 = isRow ? w1r : w1c;
    const float* b1 = isRow ? b1r : b1c;
    const float* ga = isRow ? gr  : gc;
    const float* be = isRow ? ber : bec;
    const float* w2 = isRow ? w2r : w2c;
    const float* b2 = isRow ? b2r : b2c;

    float u;
    if (a < 55) u = a * (2.0f/54.0f) - 1.0f;
    else        u = -((a-55) * (2.0f/54.0f) - 1.0f);

    float h[16];
    float mu = 0.f;
#pragma unroll
    for (int c = 0; c < 16; c++) { h[c] = u*w1[c] + b1[c]; mu += h[c]; }
    mu *= (1.0f/16.0f);
    float var = 0.f;
#pragma unroll
    for (int c = 0; c < 16; c++) { float d = h[c]-mu; var += d*d; }
    var *= (1.0f/16.0f);
    float inv = rsqrtf(var + 1e-5f);
#pragma unroll
    for (int c = 0; c < 16; c++) {
        float hn = ga[c]*(h[c]-mu)*inv + be[c];
        h[c] = hn / (1.0f + expf(-hn));
    }
    float* out = isRow ? d_Er : d_Ec;
#pragma unroll
    for (int d = 0; d < HALF; d++) {
        float s = b2[d];
#pragma unroll
        for (int c = 0; c < 16; c++) s += h[c]*w2[d*16+c];
        out[a*HALF + d] = s;
    }
}

// ---------------- q/k/v 1x1 conv, output [bh][pos][16] ----------------
__global__ void qkv_kernel(
    const float* __restrict__ x,
    const float* __restrict__ wq, const float* __restrict__ bq,
    const float* __restrict__ wk, const float* __restrict__ bk,
    const float* __restrict__ wv, const float* __restrict__ bv)
{
    int idx = blockIdx.x*blockDim.x + threadIdx.x;
    if (idx >= BATCH*HEADS*NPOS*4) return;
    int mg  = idx & 3;
    int r   = idx >> 2;
    int pos = r % NPOS;
    int r2  = r / NPOS;
    int h   = r2 & 7;
    int b   = r2 >> 3;

    float x0 = x[(b*3+0)*NPOS + pos];
    float x1 = x[(b*3+1)*NPOS + pos];
    float x2 = x[(b*3+2)*NPOS + pos];

    float4 qv, kv, vv;
    float* qp = (float*)&qv; float* kp = (float*)&kv; float* vp = (float*)&vv;
#pragma unroll
    for (int mi = 0; mi < 4; mi++) {
        int o = (mg*4 + mi)*8 + h;
        qp[mi] = bq[o] + wq[o*3+0]*x0 + wq[o*3+1]*x1 + wq[o*3+2]*x2;
        kp[mi] = bk[o] + wk[o*3+0]*x0 + wk[o*3+1]*x1 + wk[o*3+2]*x2;
        vp[mi] = bv[o] + wv[o*3+0]*x0 + wv[o*3+1]*x1 + wv[o*3+2]*x2;
    }
    size_t dst4 = ((size_t)(b*HEADS + h)*NPOS + pos)*4 + mg;
    ((float4*)d_q)[dst4] = qv;
    ((float4*)d_k)[dst4] = kv;
    ((float4*)d_v)[dst4] = vv;
}

// ---------------- fused attention: CTA per (b,h,i), 7 warps, 4 j each ----------------
// smem float4: ksh[3136] | vsh[3136] | tbl[7*56] | 1 (norm int)
#define ATTN_SMEM_BYTES ((6272 + 7*56)*16 + 16)

#define RSTEP(B, NN) { unsigned up = lane & (B);                         \
    _Pragma("unroll") for (int v = 0; v < (NN); v++) {                   \
        float send = up ? acc[v] : acc[v+(NN)];                          \
        float recv = __shfl_xor_sync(0xffffffffu, send, (B));            \
        acc[v] = (up ? acc[v+(NN)] : acc[v]) + recv; } }

__global__ void __launch_bounds__(224, 2) attn_kernel()
{
    extern __shared__ float4 sm4[];
    float4* ksh = sm4;            // [mb*784 + pos]
    float4* vsh = sm4 + 3136;
    float4* tbl = sm4 + 6272;     // [w*56 + a] : (fR[a], fC[a], fR[a+55], fC[a+55])
    int*  ctrl  = (int*)(sm4 + 6272 + 7*56);

    int t    = threadIdx.x;
    int w    = t >> 5;
    int lane = t & 31;
    int bx = blockIdx.x;
    int i  = bx % WDIM;
    int h  = (bx / WDIM) % HEADS;
    int b  = bx / (WDIM*HEADS);
    int bh = b*HEADS + h;

    const float4* gk4 = (const float4*)(d_k + (size_t)bh*NPOS*MID);
    const float4* gv4 = (const float4*)(d_v + (size_t)bh*NPOS*MID);
    const float*  gq  = d_q + (size_t)bh*NPOS*MID;

    if (t == 0) *ctrl = 0;
    for (int idx = t; idx < 3136; idx += 224) {
        int mb = idx & 3, pos = idx >> 2;
        ksh[mb*NPOS + pos] = gk4[idx];
        vsh[mb*NPOS + pos] = gv4[idx];
    }
    __syncthreads();

    // max ||k||^2
    {
        float mx = 0.f;
        for (int pos = t; pos < NPOS; pos += 224) {
            float4 k0 = ksh[pos], k1 = ksh[NPOS+pos], k2 = ksh[2*NPOS+pos], k3 = ksh[3*NPOS+pos];
            float n2 = k0.x*k0.x + k0.y*k0.y + k0.z*k0.z + k0.w*k0.w
                     + k1.x*k1.x + k1.y*k1.y + k1.z*k1.z + k1.w*k1.w
                     + k2.x*k2.x + k2.y*k2.y + k2.z*k2.z + k2.w*k2.w
                     + k3.x*k3.x + k3.y*k3.y + k3.z*k3.z + k3.w*k3.w;
            mx = fmaxf(mx, n2);
        }
#pragma unroll
        for (int off = 16; off; off >>= 1) mx = fmaxf(mx, __shfl_xor_sync(0xffffffffu, mx, off));
        if (lane == 0) atomicMax(ctrl, __float_as_int(mx));
    }
    __syncthreads();
    float maxknorm = sqrtf(__int_as_float(*ctrl));

    float* tblw = (float*)(tbl + w*56);

    for (int jj = 0; jj < 4; jj++) {
        int j = w*4 + jj;

        // q, scaled into log2 domain
        float q[16];
        {
            const float4* gq4 = (const float4*)(gq + ((size_t)(i*WDIM + j))*16);
            float4 a0 = gq4[0], a1 = gq4[1], a2 = gq4[2], a3 = gq4[3];
            q[0]=a0.x*QLOG2; q[1]=a0.y*QLOG2; q[2]=a0.z*QLOG2; q[3]=a0.w*QLOG2;
            q[4]=a1.x*QLOG2; q[5]=a1.y*QLOG2; q[6]=a1.z*QLOG2; q[7]=a1.w*QLOG2;
            q[8]=a2.x*QLOG2; q[9]=a2.y*QLOG2; q[10]=a2.z*QLOG2; q[11]=a2.w*QLOG2;
            q[12]=a3.x*QLOG2; q[13]=a3.y*QLOG2; q[14]=a3.z*QLOG2; q[15]=a3.w*QLOG2;
        }
        float qn = 0.f;
#pragma unroll
        for (int m = 0; m < 16; m++) qn += q[m]*q[m];

        // per-warp fused table + maxima
        __syncwarp();
        float mR = -1e30f, mC = -1e30f;
        for (int a = lane; a < NREL; a += 32) {
            const float4* er = (const float4*)(d_Er + a*8);
            float4 e0 = er[0], e1 = er[1];
            float fr = q[0]*e0.x + q[1]*e0.y + q[2]*e0.z + q[3]*e0.w
                     + q[4]*e1.x + q[5]*e1.y + q[6]*e1.z + q[7]*e1.w;
            const float4* ec = (const float4*)(d_Ec + a*8);
            float4 c0 = ec[0], c1 = ec[1];
            float fc = q[8]*c0.x + q[9]*c0.y + q[10]*c0.z + q[11]*c0.w
                     + q[12]*c1.x + q[13]*c1.y + q[14]*c1.z + q[15]*c1.w;
            mR = fmaxf(mR, fr); mC = fmaxf(mC, fc);
            if (a < 55) { tblw[a*4+0] = fr; tblw[a*4+1] = fc; }
            else        { tblw[(a-55)*4+2] = fr; tblw[(a-55)*4+3] = fc; }
        }
#pragma unroll
        for (int off = 16; off; off >>= 1) {
            mR = fmaxf(mR, __shfl_xor_sync(0xffffffffu, mR, off));
            mC = fmaxf(mC, __shfl_xor_sync(0xffffffffu, mC, off));
        }
        float negM = -(sqrtf(qn)*maxknorm + mR + mC);
        __syncwarp();

        // per-lane fixed-C preload (lanes 28-31 masked)
        bool valid = lane < 28;
        int lanec = valid ? lane : 27;
        int C = lanec - j + 27;
        float4 tc = tbl[w*56 + C];
        float cl0 = tc.y, cl1 = tc.z, cl2 = tc.w, cl3 = tc.x;
        if (!valid) { cl0 = cl1 = cl2 = cl3 = -1e30f; }

        float acc[64];
#pragma unroll
        for (int v = 0; v < 64; v++) acc[v] = 0.f;
        float sm0 = 0.f, sm1 = 0.f, sm2 = 0.f, sm3 = 0.f;

#pragma unroll 4
        for (int kk = 0; kk < WDIM; kk++) {
            int pos = kk*WDIM + lanec;
            float4 k0 = ksh[pos], k1 = ksh[NPOS+pos], k2 = ksh[2*NPOS+pos], k3 = ksh[3*NPOS+pos];
            float qk = q[0]*k0.x + q[1]*k0.y + q[2]*k0.z + q[3]*k0.w
                     + q[4]*k1.x + q[5]*k1.y + q[6]*k1.z + q[7]*k1.w
                     + q[8]*k2.x + q[9]*k2.y + q[10]*k2.z + q[11]*k2.w
                     + q[12]*k3.x + q[13]*k3.y + q[14]*k3.z + q[15]*k3.w + negM;

            float4 tu = tbl[w*56 + (kk - i + 27)];   // warp-uniform broadcast
            float e0 = ex2_(qk + tu.x + cl0);        // fR[R]    + fC[C]
            float e1 = ex2_(qk + tu.y + cl1);        // fC[R]    + fR[C+55]
            float e2 = ex2_(qk + tu.z + cl2);        // fR[R+55] + fC[C+55]
            float e3 = ex2_(qk + tu.w + cl3);        // fC[R+55] + fR[C]
            sm0 += e0; sm1 += e1; sm2 += e2; sm3 += e3;

            float4 v0 = vsh[pos], v1 = vsh[NPOS+pos], v2 = vsh[2*NPOS+pos], v3 = vsh[3*NPOS+pos];
            float vv[16] = {v0.x,v0.y,v0.z,v0.w, v1.x,v1.y,v1.z,v1.w,
                            v2.x,v2.y,v2.z,v2.w, v3.x,v3.y,v3.z,v3.w};
#pragma unroll
            for (int m = 0; m < 16; m++) {
                acc[ 0+m] += e0*vv[m];
                acc[16+m] += e1*vv[m];
                acc[32+m] += e2*vv[m];
                acc[48+m] += e3*vv[m];
            }
        }

        float sums[4] = {sm0, sm1, sm2, sm3};
#pragma unroll
        for (int gg = 0; gg < 4; gg++)
#pragma unroll
            for (int off = 16; off; off >>= 1)
                sums[gg] += __shfl_xor_sync(0xffffffffu, sums[gg], off);

        // value-halving butterfly: lane L ends holding values 2L, 2L+1
        RSTEP(16,32) RSTEP(8,16) RSTEP(4,8) RSTEP(2,4) RSTEP(1,2)

#pragma unroll
        for (int q2 = 0; q2 < 2; q2++) {
            int v = 2*lane + q2;
            int g = v >> 4, m = v & 15;
            d_outv[(((size_t)(b*G + g)*NPOS) + i*WDIM + j)*128 + m*8 + h] = acc[q2] / sums[g];
        }
    }
}

// ---------------- output 1x1 conv, FFMA2 tiled SGEMM (64x64, 196 blocks) ----------------
#define OPAD 68
#define OUT_SMEM_BYTES (2*128*OPAD*4)
__global__ void __launch_bounds__(256, 2) out_gemm(const float* __restrict__ wout,
                                                   const float* __restrict__ bout,
                                                   float* __restrict__ out)
{
    extern __shared__ float osh[];
    float* Xs = osh;               // [k][r], stride OPAD
    float* Ws = osh + 128*OPAD;    // [k][c], stride OPAD

    int t = threadIdx.x;
    int Rbase = blockIdx.x * 64;

    for (int idx = t; idx < 2048; idx += 256) {
        int r = idx & 63, c4 = idx >> 6;
        float4 val = ((const float4*)d_outv)[(size_t)(Rbase + r)*32 + c4];
        Xs[(4*c4+0)*OPAD + r] = val.x;
        Xs[(4*c4+1)*OPAD + r] = val.y;
        Xs[(4*c4+2)*OPAD + r] = val.z;
        Xs[(4*c4+3)*OPAD + r] = val.w;
    }
    for (int idx = t; idx < 2048; idx += 256) {
        int o = idx & 63, c4 = idx >> 6;
        float4 val = ((const float4*)wout)[o*32 + c4];
        Ws[(4*c4+0)*OPAD + o] = val.x;
        Ws[(4*c4+1)*OPAD + o] = val.y;
        Ws[(4*c4+2)*OPAD + o] = val.z;
        Ws[(4*c4+3)*OPAD + o] = val.w;
    }
    __syncthreads();

    int tx = t & 15, ty = t >> 4;   // rows 4tx..+3, cols 4ty..+3
    ull a0c01=0, a0c23=0, a1c01=0, a1c23=0, a2c01=0, a2c23=0, a3c01=0, a3c23=0;

#pragma unroll 8
    for (int k = 0; k < 128; k++) {
        float4 av = *(const float4*)&Xs[k*OPAD + 4*tx];
        ulonglong2 bv = *(const ulonglong2*)&Ws[k*OPAD + 4*ty];
        ull ab0 = pk2(av.x, av.x), ab1 = pk2(av.y, av.y);
        ull ab2 = pk2(av.z, av.z), ab3 = pk2(av.w, av.w);
        a0c01 = fma2_(ab0, bv.x, a0c01);  a0c23 = fma2_(ab0, bv.y, a0c23);
        a1c01 = fma2_(ab1, bv.x, a1c01);  a1c23 = fma2_(ab1, bv.y, a1c23);
        a2c01 = fma2_(ab2, bv.x, a2c01);  a2c23 = fma2_(ab2, bv.y, a2c23);
        a3c01 = fma2_(ab3, bv.x, a3c01);  a3c23 = fma2_(ab3, bv.y, a3c23);
    }

    ull accs[4][2] = {{a0c01,a0c23},{a1c01,a1c23},{a2c01,a2c23},{a3c01,a3c23}};
    float bia[4];
#pragma unroll
    for (int ci = 0; ci < 4; ci++) bia[ci] = bout[4*ty + ci];

#pragma unroll
    for (int ri = 0; ri < 4; ri++) {
        int R = Rbase + 4*tx + ri;
        int bb = R / (G*NPOS);
        int rem = R - bb*(G*NPOS);
        int g = rem / NPOS;
        int pos = rem - g*NPOS;
        float o0, o1, o2, o3;
        upk2(accs[ri][0], o0, o1);
        upk2(accs[ri][1], o2, o3);
        size_t ob = (((size_t)(bb*COUT + 4*ty))*G + g)*NPOS + pos;
        out[ob]            = o0 + bia[0];
        out[ob + G*NPOS]   = o1 + bia[1];
        out[ob + 2*G*NPOS] = o2 + bia[2];
        out[ob + 3*G*NPOS] = o3 + bia[3];
    }
}

// ---------------- launch ----------------
extern "C" void kernel_launch(void* const* d_in, const int* in_sizes, int n_in,
                              void* d_out, int out_size)
{
    const float* x     = (const float*)d_in[0];
    const float* wq    = (const float*)d_in[1];
    const float* bq    = (const float*)d_in[2];
    const float* wk    = (const float*)d_in[3];
    const float* bk    = (const float*)d_in[4];
    const float* wv    = (const float*)d_in[5];
    const float* bv    = (const float*)d_in[6];
    const float* w_out = (const float*)d_in[7];
    const float* b_out = (const float*)d_in[8];
    const float* row_w1 = (const float*)d_in[9];
    const float* row_b1 = (const float*)d_in[10];
    const float* row_g  = (const float*)d_in[11];
    const float* row_be = (const float*)d_in[12];
    const float* row_w2 = (const float*)d_in[13];
    const float* row_b2 = (const float*)d_in[14];
    const float* col_w1 = (const float*)d_in[15];
    const float* col_b1 = (const float*)d_in[16];
    const float* col_g  = (const float*)d_in[17];
    const float* col_be = (const float*)d_in[18];
    const float* col_w2 = (const float*)d_in[19];
    const float* col_b2 = (const float*)d_in[20];

    cudaFuncSetAttribute(attn_kernel, cudaFuncAttributeMaxDynamicSharedMemorySize, ATTN_SMEM_BYTES);
    cudaFuncSetAttribute(out_gemm,    cudaFuncAttributeMaxDynamicSharedMemorySize, OUT_SMEM_BYTES);

    embed_kernel<<<1, 256>>>(row_w1, row_b1, row_g, row_be, row_w2, row_b2,
                             col_w1, col_b1, col_g, col_be, col_w2, col_b2);

    int qkv_threads = BATCH*HEADS*NPOS*4;
    qkv_kernel<<<(qkv_threads + 255)/256, 256>>>(x, wq, bq, wk, bk, wv, bv);

    attn_kernel<<<BATCH*HEADS*WDIM, 224, ATTN_SMEM_BYTES>>>();

    out_gemm<<<196, 256, OUT_SMEM_BYTES>>>(w_out, b_out, (float*)d_out);
}